// round 2
// baseline (speedup 1.0000x reference)
#include <cuda_runtime.h>
#include <cstdint>

#define NB 16
#define NC 256
#define NT 2048
#define NROWS (NB*NT)          // 32768
#define NCODES 8192
#define NQ (NB*NC*NT)          // 8388608
#define BM 128
#define BN 128
#define BK 16
#define LDA 132

__device__ float g_zt[(size_t)NROWS * NC];
__device__ float g_zz[NROWS];
__device__ float g_ee[NCODES];
__device__ int   g_idx[NROWS];
__device__ float g_losspart[NQ / 256];

// ---- transpose z [B,C,T] -> g_zt [B*T, C] ----
__global__ void k_transpose(const float* __restrict__ z) {
    __shared__ float tile[64][65];
    int r0 = blockIdx.x * 64;
    int b = r0 >> 11, t0 = r0 & 2047;
    const float* zb = z + (size_t)b * NC * NT;
    for (int c0 = 0; c0 < NC; c0 += 64) {
        for (int i = threadIdx.x; i < 64 * 64; i += 256) {
            int cl = i >> 6, tl = i & 63;
            tile[cl][tl] = zb[(size_t)(c0 + cl) * NT + t0 + tl];
        }
        __syncthreads();
        for (int i = threadIdx.x; i < 64 * 64; i += 256) {
            int rl = i >> 6, cl = i & 63;
            g_zt[(size_t)(r0 + rl) * NC + c0 + cl] = tile[cl][rl];
        }
        __syncthreads();
    }
}

// ---- row squared norms: mode 0 g_zt->g_zz, mode 1 ext->g_ee ----
__global__ void k_rownorm(const float* __restrict__ ext, int mode) {
    int row = blockIdx.x * 8 + (threadIdx.x >> 5);
    int lane = threadIdx.x & 31;
    const float* src = (mode == 0) ? g_zt : ext;
    const float4* p = reinterpret_cast<const float4*>(src + (size_t)row * NC);
    float s = 0.f;
#pragma unroll
    for (int j = 0; j < 2; j++) {
        float4 v = p[lane + 32 * j];
        s += v.x * v.x + v.y * v.y + v.z * v.z + v.w * v.w;
    }
#pragma unroll
    for (int o = 16; o > 0; o >>= 1) s += __shfl_xor_sync(0xffffffffu, s, o);
    if (lane == 0) { if (mode == 0) g_zz[row] = s; else g_ee[row] = s; }
}

// ---- fused fp32 GEMM + lexicographic argmin ----
__device__ __forceinline__ void sts_tile(float (*A)[LDA], int rl, int c4, float4 v) {
    A[c4 * 4 + 0][rl] = v.x; A[c4 * 4 + 1][rl] = v.y;
    A[c4 * 4 + 2][rl] = v.z; A[c4 * 4 + 3][rl] = v.w;
}

__global__ void __launch_bounds__(256, 2) k_gemm(const float* __restrict__ cb) {
    __shared__ union SH {
        struct { float A[2][BK][LDA]; float B[2][BK][LDA]; } g;
        unsigned long long red[BM][16];
    } sm;
    const int tid = threadIdx.x;
    const int tx = tid & 15, ty = tid >> 4;
    const int r0 = blockIdx.x * BM;
    const int rl0 = tid >> 2, rl1 = (tid >> 2) + 64, c4 = tid & 3;

    float zzr[8];
#pragma unroll
    for (int i = 0; i < 8; i++) zzr[i] = g_zz[r0 + ty * 8 + i];
    unsigned long long best[8];
#pragma unroll
    for (int i = 0; i < 8; i++) best[i] = ~0ull;

    for (int n0 = 0; n0 < NCODES; n0 += BN) {
        float acc[8][8];
#pragma unroll
        for (int i = 0; i < 8; i++)
#pragma unroll
            for (int j = 0; j < 8; j++) acc[i][j] = 0.f;

        sts_tile(sm.g.A[0], rl0, c4, *reinterpret_cast<const float4*>(&g_zt[(size_t)(r0 + rl0) * NC + c4 * 4]));
        sts_tile(sm.g.A[0], rl1, c4, *reinterpret_cast<const float4*>(&g_zt[(size_t)(r0 + rl1) * NC + c4 * 4]));
        sts_tile(sm.g.B[0], rl0, c4, *reinterpret_cast<const float4*>(&cb[(size_t)(n0 + rl0) * NC + c4 * 4]));
        sts_tile(sm.g.B[0], rl1, c4, *reinterpret_cast<const float4*>(&cb[(size_t)(n0 + rl1) * NC + c4 * 4]));
        __syncthreads();

        int cur = 0;
        float4 pa0, pa1, pb0, pb1;
        for (int kk = 0; kk < NC / BK; kk++) {
            if (kk < NC / BK - 1) {
                int ko = (kk + 1) * BK + c4 * 4;
                pa0 = *reinterpret_cast<const float4*>(&g_zt[(size_t)(r0 + rl0) * NC + ko]);
                pa1 = *reinterpret_cast<const float4*>(&g_zt[(size_t)(r0 + rl1) * NC + ko]);
                pb0 = *reinterpret_cast<const float4*>(&cb[(size_t)(n0 + rl0) * NC + ko]);
                pb1 = *reinterpret_cast<const float4*>(&cb[(size_t)(n0 + rl1) * NC + ko]);
            }
#pragma unroll
            for (int k = 0; k < BK; k++) {
                float4 a0 = *reinterpret_cast<const float4*>(&sm.g.A[cur][k][ty * 8]);
                float4 a1 = *reinterpret_cast<const float4*>(&sm.g.A[cur][k][ty * 8 + 4]);
                float4 b0 = *reinterpret_cast<const float4*>(&sm.g.B[cur][k][tx * 8]);
                float4 b1 = *reinterpret_cast<const float4*>(&sm.g.B[cur][k][tx * 8 + 4]);
                float av[8] = {a0.x, a0.y, a0.z, a0.w, a1.x, a1.y, a1.z, a1.w};
                float bv[8] = {b0.x, b0.y, b0.z, b0.w, b1.x, b1.y, b1.z, b1.w};
#pragma unroll
                for (int i = 0; i < 8; i++)
#pragma unroll
                    for (int j = 0; j < 8; j++)
                        acc[i][j] = fmaf(av[i], bv[j], acc[i][j]);
            }
            if (kk < NC / BK - 1) {
                __syncthreads();
                sts_tile(sm.g.A[cur ^ 1], rl0, c4, pa0);
                sts_tile(sm.g.A[cur ^ 1], rl1, c4, pa1);
                sts_tile(sm.g.B[cur ^ 1], rl0, c4, pb0);
                sts_tile(sm.g.B[cur ^ 1], rl1, c4, pb1);
                __syncthreads();
                cur ^= 1;
            }
        }
#pragma unroll
        for (int j = 0; j < 8; j++) {
            int code = n0 + tx * 8 + j;
            float eej = __ldg(&g_ee[code]);
#pragma unroll
            for (int i = 0; i < 8; i++) {
                float s = __fadd_rn(zzr[i], eej);
                float d = __fadd_rn(s, -2.0f * acc[i][j]);
                unsigned long long key =
                    ((unsigned long long)__float_as_uint(d) << 13) | (unsigned long long)code;
                if (key < best[i]) best[i] = key;
            }
        }
    }
    __syncthreads();
#pragma unroll
    for (int i = 0; i < 8; i++) sm.red[ty * 8 + i][tx] = best[i];
    __syncthreads();
    if (tid < BM) {
        unsigned long long m = sm.red[tid][0];
#pragma unroll
        for (int t = 1; t < 16; t++) { unsigned long long v = sm.red[tid][t]; if (v < m) m = v; }
        g_idx[r0 + tid] = (int)(m & 8191u);
    }
}

// ---- z_q_ste + per-block loss partials ----
__global__ void k_output(const float* __restrict__ z, const float* __restrict__ cb,
                         float* __restrict__ out) {
    __shared__ float warp_s[8];
    int e = blockIdx.x * 256 + threadIdx.x;
    int t = e & 2047, bc = e >> 11, c = bc & 255, b = bc >> 8;
    int code = g_idx[b * 2048 + t];
    float v = z[e];
    float zq = cb[(size_t)code * NC + c];
    float d = zq - v;
    out[e] = v + d;                      // z + (z_q - z), replicates STE rounding
    float s = d * d;
#pragma unroll
    for (int o = 16; o > 0; o >>= 1) s += __shfl_xor_sync(0xffffffffu, s, o);
    if ((threadIdx.x & 31) == 0) warp_s[threadIdx.x >> 5] = s;
    __syncthreads();
    if (threadIdx.x == 0) {
        float acc = 0.f;
#pragma unroll
        for (int w = 0; w < 8; w++) acc += warp_s[w];
        g_losspart[blockIdx.x] = acc;
    }
}

// ---- indices (blocks 0..127) + deterministic loss reduce (block 128) ----
__global__ void k_final(float* __restrict__ out) {
    if (blockIdx.x < 128) {
        int i = blockIdx.x * 256 + threadIdx.x;
        out[NQ + i] = (float)g_idx[i];
    } else {
        __shared__ double ds[256];
        double a = 0.0;
        for (int i = threadIdx.x; i < NQ / 256; i += 256) a += (double)g_losspart[i];
        ds[threadIdx.x] = a;
        __syncthreads();
        for (int o = 128; o > 0; o >>= 1) {
            if (threadIdx.x < o) ds[threadIdx.x] += ds[threadIdx.x + o];
            __syncthreads();
        }
        if (threadIdx.x == 0) out[NQ + NROWS] = (float)(ds[0] / (double)NQ);
    }
}

extern "C" void kernel_launch(void* const* d_in, const int* in_sizes, int n_in,
                              void* d_out, int out_size) {
    const float* z  = (const float*)d_in[0];
    const float* cb = (const float*)d_in[1];
    float* out = (float*)d_out;
    k_transpose<<<NROWS / 64, 256>>>(z);
    k_rownorm<<<NROWS / 8, 256>>>(nullptr, 0);
    k_rownorm<<<NCODES / 8, 256>>>(cb, 1);
    k_gemm<<<NROWS / BM, 256>>>(cb);
    k_output<<<NQ / 256, 256>>>(z, cb, out);
    k_final<<<129, 256>>>(out);
}

// round 4
// speedup vs baseline: 1.2436x; 1.2436x over previous
#include <cuda_runtime.h>
#include <cuda_bf16.h>
#include <cstdint>

#define NB 16
#define NC 256
#define NT 2048
#define NROWS (NB*NT)          // 32768
#define NCODES 8192
#define NQ (NB*NC*NT)          // 8388608
#define CANDMAX 64
#define MARGIN 1.0e-3f

// ---------------- device scratch ----------------
__device__ float g_zt[(size_t)NROWS * NC];
__device__ __nv_bfloat16 g_ztb[(size_t)NROWS * NC];
__device__ __nv_bfloat16 g_cbb[(size_t)NCODES * NC];
__device__ float g_zz[NROWS];
__device__ float g_ee[NCODES];
__device__ int   g_idx[NROWS];
__device__ float g_losspart[NQ / 256];
__device__ float g_cand_s[(size_t)NROWS * CANDMAX];
__device__ int   g_cand_c[(size_t)NROWS * CANDMAX];
__device__ unsigned int g_bestu[NROWS];
__device__ int   g_cnt[NROWS];

// ---------------- helpers ----------------
__device__ __forceinline__ uint32_t smem_u32(const void* p) {
    uint32_t a;
    asm("{ .reg .u64 t; cvta.to.shared.u64 t, %1; cvt.u32.u64 %0, t; }" : "=r"(a) : "l"(p));
    return a;
}
__device__ __forceinline__ void cp16(uint32_t dst, const void* src) {
    unsigned long long g = __cvta_generic_to_global(src);
    asm volatile("cp.async.cg.shared.global [%0], [%1], 16;" :: "r"(dst), "l"(g) : "memory");
}
#define CP_COMMIT() asm volatile("cp.async.commit_group;" ::: "memory")
#define CP_WAIT0()  asm volatile("cp.async.wait_group 0;" ::: "memory")
#define SWZ(x) ((x) ^ (((x) >> 3) & 0x70))

__device__ __forceinline__ void ldsm_x4(uint32_t* r, uint32_t a) {
    asm volatile("ldmatrix.sync.aligned.m8n8.x4.shared.b16 {%0,%1,%2,%3}, [%4];"
        : "=r"(r[0]), "=r"(r[1]), "=r"(r[2]), "=r"(r[3]) : "r"(a));
}
__device__ __forceinline__ void mma16816(float* c, const uint32_t* a, uint32_t b0, uint32_t b1) {
    asm volatile("mma.sync.aligned.m16n8k16.row.col.f32.bf16.bf16.f32 "
        "{%0,%1,%2,%3}, {%4,%5,%6,%7}, {%8,%9}, {%0,%1,%2,%3};"
        : "+f"(c[0]), "+f"(c[1]), "+f"(c[2]), "+f"(c[3])
        : "r"(a[0]), "r"(a[1]), "r"(a[2]), "r"(a[3]), "r"(b0), "r"(b1));
}

// smem layout: A@1024 (64KB), B@66560 (2x64KB), ee@197632 (32KB)
#define A_OFF   1024
#define B_OFF   66560
#define EE_OFF  197632
#define SMEMT   230400

// tile layout: offset(r, c_half) = (c>>6)*16384 + (r>>3)*1024 + SWZ((r&7)*128 + (c&63)*2)
__device__ __forceinline__ uint32_t tile_addr(uint32_t base, int r, int c) {
    return base + ((c >> 6) << 14) + ((r >> 3) << 10) + SWZ((r & 7) * 128 + (c & 63) * 2);
}

// ---------------- kernels ----------------
__global__ void k_transpose(const float* __restrict__ z) {
    __shared__ float tile[64][65];
    int r0 = blockIdx.x * 64;
    int b = r0 >> 11, t0 = r0 & 2047;
    const float* zb = z + (size_t)b * NC * NT;
    for (int c0 = 0; c0 < NC; c0 += 64) {
        for (int i = threadIdx.x; i < 64 * 64; i += 256) {
            int cl = i >> 6, tl = i & 63;
            tile[cl][tl] = zb[(size_t)(c0 + cl) * NT + t0 + tl];
        }
        __syncthreads();
        for (int i = threadIdx.x; i < 64 * 64; i += 256) {
            int rl = i >> 6, cl = i & 63;
            float v = tile[cl][rl];
            size_t o = (size_t)(r0 + rl) * NC + c0 + cl;
            g_zt[o] = v;
            g_ztb[o] = __float2bfloat16(v);
        }
        __syncthreads();
    }
}

__global__ void k_cbconv(const float* __restrict__ cb) {
    int i = blockIdx.x * 256 + threadIdx.x;
    g_cbb[i] = __float2bfloat16(cb[i]);
}

__global__ void k_init() {
    int i = blockIdx.x * 256 + threadIdx.x;
    if (i < NROWS) { g_cnt[i] = 0; g_bestu[i] = 0x7F800000u; }
}

__global__ void k_rownorm(const float* __restrict__ ext, int mode) {
    int row = blockIdx.x * 8 + (threadIdx.x >> 5);
    int lane = threadIdx.x & 31;
    const float* src = (mode == 0) ? g_zt : ext;
    const float4* p = reinterpret_cast<const float4*>(src + (size_t)row * NC);
    float s = 0.f;
#pragma unroll
    for (int j = 0; j < 2; j++) {
        float4 v = p[lane + 32 * j];
        s += v.x * v.x + v.y * v.y + v.z * v.z + v.w * v.w;
    }
#pragma unroll
    for (int o = 16; o > 0; o >>= 1) s += __shfl_xor_sync(0xffffffffu, s, o);
    if (lane == 0) { if (mode == 0) g_zz[row] = s; else g_ee[row] = s; }
}

// load one 128x256-bf16 tile (64KB) into swizzled smem via cp.async (256 threads)
__device__ __forceinline__ void issue_tile(const __nv_bfloat16* src, uint32_t base, int tid) {
    const char* s0 = (const char*)src;
    for (int idx = tid; idx < 4096; idx += 256) {
        int r = idx >> 5, ch = idx & 31;       // 32 x 16B per row
        int cc = ch * 8;                        // half-column
        cp16(tile_addr(base, r, cc), s0 + (size_t)r * 512 + ch * 16);
    }
}

__global__ void __launch_bounds__(256, 1) k_screen() {
    extern __shared__ char smem[];
    uint32_t sb = smem_u32(smem);
    const int tid = threadIdx.x, lane = tid & 31, wid = tid >> 5;
    const int wm = wid >> 1, wn = wid & 1;     // warp grid 4 (M) x 2 (N)
    const int r0 = blockIdx.x * 128;
    const int g4 = lane >> 2, q4 = lane & 3;

    float* ees = (float*)(smem + EE_OFF);
    for (int i = tid; i < NCODES; i += 256) ees[i] = g_ee[i];

    issue_tile(g_ztb + (size_t)r0 * NC, sb + A_OFF, tid);
    issue_tile(g_cbb, sb + B_OFF, tid);
    CP_COMMIT();

    float zzr[2][2], lb[2][2];
#pragma unroll
    for (int mt = 0; mt < 2; mt++)
#pragma unroll
        for (int h = 0; h < 2; h++) {
            zzr[mt][h] = g_zz[r0 + wm * 32 + mt * 16 + h * 8 + g4];
            lb[mt][h] = 3.0e38f;
        }

    // ldmatrix lane address components (same pattern for A and B-transposed)
    const int lrow = ((lane >> 3) & 1) * 8 + (lane & 7);  // row within 16-row tile
    const int lcol = (lane >> 4) * 8;                      // k offset 0 or 8

    for (int c = 0; c < 64; c++) {
        CP_WAIT0();
        __syncthreads();
        if (c + 1 < 64)
            issue_tile(g_cbb + (size_t)(c + 1) * 128 * NC, sb + B_OFF + ((c + 1) & 1) * 65536, tid);
        CP_COMMIT();

        const uint32_t bbase = sb + B_OFF + (c & 1) * 65536;
        float acc[2][8][4];
#pragma unroll
        for (int mt = 0; mt < 2; mt++)
#pragma unroll
            for (int nt = 0; nt < 8; nt++)
#pragma unroll
                for (int e = 0; e < 4; e++) acc[mt][nt][e] = 0.f;

#pragma unroll
        for (int kk = 0; kk < 16; kk++) {
            int k0 = kk * 16 + lcol;
            uint32_t a[2][4], b[4][4];
#pragma unroll
            for (int mt = 0; mt < 2; mt++)
                ldsm_x4(a[mt], tile_addr(sb + A_OFF, wm * 32 + mt * 16 + lrow, k0));
#pragma unroll
            for (int p = 0; p < 4; p++)
                ldsm_x4(b[p], tile_addr(bbase, wn * 64 + p * 16 + lrow, k0));
#pragma unroll
            for (int mt = 0; mt < 2; mt++)
#pragma unroll
                for (int nt = 0; nt < 8; nt++) {
                    int p = nt >> 1, o = nt & 1;
                    mma16816(acc[mt][nt], a[mt], b[p][o], b[p][o + 2]);
                }
        }

        // ---- epilogue: scores, per-row chunk min, candidate append ----
        float nb[2][2];
#pragma unroll
        for (int mt = 0; mt < 2; mt++)
#pragma unroll
            for (int h = 0; h < 2; h++) {
                float zze = zzr[mt][h];
                float m = 3.0e38f;
#pragma unroll
                for (int nt = 0; nt < 8; nt++)
#pragma unroll
                    for (int e = 0; e < 2; e++) {
                        int code = c * 128 + wn * 64 + nt * 8 + q4 * 2 + e;
                        float s = fmaf(-2.0f, acc[mt][nt][h * 2 + e], zze + ees[code]);
                        acc[mt][nt][h * 2 + e] = s;
                        m = fminf(m, s);
                    }
                m = fminf(m, __shfl_xor_sync(0xffffffffu, m, 1));
                m = fminf(m, __shfl_xor_sync(0xffffffffu, m, 2));
                nb[mt][h] = fminf(lb[mt][h], m);
            }
#pragma unroll
        for (int mt = 0; mt < 2; mt++)
#pragma unroll
            for (int h = 0; h < 2; h++) {
                float thr = nb[mt][h] + MARGIN;
                int row = r0 + wm * 32 + mt * 16 + h * 8 + g4;
#pragma unroll
                for (int nt = 0; nt < 8; nt++)
#pragma unroll
                    for (int e = 0; e < 2; e++) {
                        float s = acc[mt][nt][h * 2 + e];
                        if (s < thr) {
                            int code = c * 128 + wn * 64 + nt * 8 + q4 * 2 + e;
                            int slot = atomicAdd(&g_cnt[row], 1);
                            if (slot < CANDMAX) {
                                g_cand_s[(size_t)row * CANDMAX + slot] = s;
                                g_cand_c[(size_t)row * CANDMAX + slot] = code;
                            }
                            atomicMin(&g_bestu[row], __float_as_uint(s));
                        }
                    }
                lb[mt][h] = nb[mt][h];
            }
    }
}

// exact fp32 rescore of surviving candidates; one warp per row
__global__ void k_rescore(const float* __restrict__ cb) {
    int row = blockIdx.x * 8 + (threadIdx.x >> 5);
    int lane = threadIdx.x & 31;
    const float4* zr = reinterpret_cast<const float4*>(g_zt + (size_t)row * NC);
    float4 z0 = zr[lane * 2], z1 = zr[lane * 2 + 1];
    float zzr = g_zz[row];
    int cnt = g_cnt[row];
    float bs = __uint_as_float(g_bestu[row]);
    unsigned long long bkey = ~0ull;

    auto eval = [&](int code) {
        const float4* er = reinterpret_cast<const float4*>(cb + (size_t)code * NC);
        float4 e0 = er[lane * 2], e1 = er[lane * 2 + 1];
        float p = z0.x * e0.x + z0.y * e0.y + z0.z * e0.z + z0.w * e0.w
                + z1.x * e1.x + z1.y * e1.y + z1.z * e1.z + z1.w * e1.w;
#pragma unroll
        for (int o = 16; o > 0; o >>= 1) p += __shfl_xor_sync(0xffffffffu, p, o);
        float d = __fadd_rn(__fadd_rn(zzr, g_ee[code]), -2.0f * p);
        unsigned long long key =
            ((unsigned long long)__float_as_uint(d) << 13) | (unsigned long long)code;
        if (key < bkey) bkey = key;
    };

    if (cnt > CANDMAX) {
        for (int code = 0; code < NCODES; code++) eval(code);
    } else {
        size_t crow = (size_t)row * CANDMAX;
        for (int i = 0; i < cnt; i++) {
            float si = g_cand_s[crow + i];
            if (si > bs + MARGIN) continue;
            eval(g_cand_c[crow + i]);
        }
    }
    if (lane == 0) g_idx[row] = (int)(bkey & 8191u);
}

__global__ void k_output(const float* __restrict__ z, const float* __restrict__ cb,
                         float* __restrict__ out) {
    __shared__ float warp_s[8];
    int e = blockIdx.x * 256 + threadIdx.x;
    int t = e & 2047, bc = e >> 11, c = bc & 255, b = bc >> 8;
    int code = g_idx[b * 2048 + t];
    float v = z[e];
    float zq = cb[(size_t)code * NC + c];
    float d = zq - v;
    out[e] = v + d;
    float s = d * d;
#pragma unroll
    for (int o = 16; o > 0; o >>= 1) s += __shfl_xor_sync(0xffffffffu, s, o);
    if ((threadIdx.x & 31) == 0) warp_s[threadIdx.x >> 5] = s;
    __syncthreads();
    if (threadIdx.x == 0) {
        float acc = 0.f;
#pragma unroll
        for (int w = 0; w < 8; w++) acc += warp_s[w];
        g_losspart[blockIdx.x] = acc;
    }
}

__global__ void k_final(float* __restrict__ out) {
    if (blockIdx.x < 128) {
        int i = blockIdx.x * 256 + threadIdx.x;
        out[NQ + i] = (float)g_idx[i];
    } else {
        __shared__ double ds[256];
        double a = 0.0;
        for (int i = threadIdx.x; i < NQ / 256; i += 256) a += (double)g_losspart[i];
        ds[threadIdx.x] = a;
        __syncthreads();
        for (int o = 128; o > 0; o >>= 1) {
            if (threadIdx.x < o) ds[threadIdx.x] += ds[threadIdx.x + o];
            __syncthreads();
        }
        if (threadIdx.x == 0) out[NQ + NROWS] = (float)(ds[0] / (double)NQ);
    }
}

extern "C" void kernel_launch(void* const* d_in, const int* in_sizes, int n_in,
                              void* d_out, int out_size) {
    const float* z  = (const float*)d_in[0];
    const float* cb = (const float*)d_in[1];
    float* out = (float*)d_out;
    cudaFuncSetAttribute(k_screen, cudaFuncAttributeMaxDynamicSharedMemorySize, SMEMT);
    k_transpose<<<NROWS / 64, 256>>>(z);
    k_cbconv<<<(NCODES * NC) / 256, 256>>>(cb);
    k_init<<<NROWS / 256, 256>>>();
    k_rownorm<<<NROWS / 8, 256>>>(nullptr, 0);
    k_rownorm<<<NCODES / 8, 256>>>(cb, 1);
    k_screen<<<NROWS / 128, 256, SMEMT>>>();
    k_rescore<<<NROWS / 8, 256>>>(cb);
    k_output<<<NQ / 256, 256>>>(z, cb, out);
    k_final<<<129, 256>>>(out);
}

// round 5
// speedup vs baseline: 1.2871x; 1.0350x over previous
#include <cuda_runtime.h>
#include <cuda_bf16.h>
#include <cstdint>

#define NB 16
#define NC 256
#define NT 2048
#define NROWS (NB*NT)          // 32768
#define NCODES 8192
#define NQ (NB*NC*NT)          // 8388608
#define CANDMAX 64
#define MARGIN 1.0e-3f
#define CHUNKS_PER_LAUNCH 16

// ---------------- device scratch ----------------
__device__ float g_zt[(size_t)NROWS * NC];
__device__ __nv_bfloat16 g_ztb[(size_t)NROWS * NC];
__device__ __nv_bfloat16 g_cbb[(size_t)NCODES * NC];
__device__ float g_zz[NROWS];
__device__ float g_ee[NCODES];
__device__ int   g_idx[NROWS];
__device__ float g_losspart[NQ / 256];
__device__ float g_cand_s[(size_t)NROWS * CANDMAX];
__device__ int   g_cand_c[(size_t)NROWS * CANDMAX];
__device__ unsigned int g_bestu[NROWS];
__device__ int   g_cnt[NROWS];

// ---------------- helpers ----------------
__device__ __forceinline__ uint32_t smem_u32(const void* p) {
    uint32_t a;
    asm("{ .reg .u64 t; cvta.to.shared.u64 t, %1; cvt.u32.u64 %0, t; }" : "=r"(a) : "l"(p));
    return a;
}
__device__ __forceinline__ void cp16(uint32_t dst, const void* src) {
    unsigned long long g = __cvta_generic_to_global(src);
    asm volatile("cp.async.cg.shared.global [%0], [%1], 16;" :: "r"(dst), "l"(g) : "memory");
}
#define CP_COMMIT() asm volatile("cp.async.commit_group;" ::: "memory")
#define CP_WAIT0()  asm volatile("cp.async.wait_group 0;" ::: "memory")
#define SWZ(x) ((x) ^ (((x) >> 3) & 0x70))

__device__ __forceinline__ void ldsm_x4(uint32_t* r, uint32_t a) {
    asm volatile("ldmatrix.sync.aligned.m8n8.x4.shared.b16 {%0,%1,%2,%3}, [%4];"
        : "=r"(r[0]), "=r"(r[1]), "=r"(r[2]), "=r"(r[3]) : "r"(a));
}
__device__ __forceinline__ void mma16816(float* c, const uint32_t* a, uint32_t b0, uint32_t b1) {
    asm volatile("mma.sync.aligned.m16n8k16.row.col.f32.bf16.bf16.f32 "
        "{%0,%1,%2,%3}, {%4,%5,%6,%7}, {%8,%9}, {%0,%1,%2,%3};"
        : "+f"(c[0]), "+f"(c[1]), "+f"(c[2]), "+f"(c[3])
        : "r"(a[0]), "r"(a[1]), "r"(a[2]), "r"(a[3]), "r"(b0), "r"(b1));
}

#define A_OFF   1024
#define B_OFF   66560
#define EE_OFF  197632
#define SMEMT   230400

__device__ __forceinline__ uint32_t tile_addr(uint32_t base, int r, int c) {
    return base + ((c >> 6) << 14) + ((r >> 3) << 10) + SWZ((r & 7) * 128 + (c & 63) * 2);
}

// ---------------- prep kernels ----------------
__global__ void k_transpose(const float* __restrict__ z) {
    __shared__ float tile[64][65];
    int r0 = blockIdx.x * 64;
    int b = r0 >> 11, t0 = r0 & 2047;
    const float* zb = z + (size_t)b * NC * NT;
    for (int c0 = 0; c0 < NC; c0 += 64) {
        for (int i = threadIdx.x; i < 64 * 64; i += 256) {
            int cl = i >> 6, tl = i & 63;
            tile[cl][tl] = zb[(size_t)(c0 + cl) * NT + t0 + tl];
        }
        __syncthreads();
        for (int i = threadIdx.x; i < 64 * 64; i += 256) {
            int rl = i >> 6, cl = i & 63;
            float v = tile[cl][rl];
            size_t o = (size_t)(r0 + rl) * NC + c0 + cl;
            g_zt[o] = v;
            g_ztb[o] = __float2bfloat16(v);
        }
        __syncthreads();
    }
}

// codebook bf16 convert + per-row state init
__global__ void k_prep(const float* __restrict__ cb) {
    int i = blockIdx.x * 256 + threadIdx.x;
    g_cbb[i] = __float2bfloat16(cb[i]);
    if (i < NROWS) { g_cnt[i] = 0; g_bestu[i] = 0x7F800000u; }
}

// fused norms: blocks [0, NROWS/8) -> zz, rest -> ee
__global__ void k_norms(const float* __restrict__ cb) {
    int gr = blockIdx.x * 8 + (threadIdx.x >> 5);
    int lane = threadIdx.x & 31;
    const float* src;
    if (gr < NROWS) src = g_zt + (size_t)gr * NC;
    else            src = cb + (size_t)(gr - NROWS) * NC;
    const float4* p = reinterpret_cast<const float4*>(src);
    float s = 0.f;
#pragma unroll
    for (int j = 0; j < 2; j++) {
        float4 v = p[lane + 32 * j];
        s += v.x * v.x + v.y * v.y + v.z * v.z + v.w * v.w;
    }
#pragma unroll
    for (int o = 16; o > 0; o >>= 1) s += __shfl_xor_sync(0xffffffffu, s, o);
    if (lane == 0) { if (gr < NROWS) g_zz[gr] = s; else g_ee[gr - NROWS] = s; }
}

// load one 128x256-bf16 tile (64KB) into swizzled smem via cp.async (256 threads)
__device__ __forceinline__ void issue_tile(const __nv_bfloat16* src, uint32_t base, int tid) {
    const char* s0 = (const char*)src;
    for (int idx = tid; idx < 4096; idx += 256) {
        int r = idx >> 5, ch = idx & 31;
        cp16(tile_addr(base, r, ch * 8), s0 + (size_t)r * 512 + ch * 16);
    }
}

// ---------------- screening (bf16 mma, per-launch chunk range) ----------------
__global__ void __launch_bounds__(256, 1) k_screen(int c0) {
    extern __shared__ char smem[];
    uint32_t sb = smem_u32(smem);
    const int tid = threadIdx.x, lane = tid & 31, wid = tid >> 5;
    const int wm = wid >> 1, wn = wid & 1;
    const int r0 = blockIdx.x * 128;
    const int g4 = lane >> 2, q4 = lane & 3;

    float* ees = (float*)(smem + EE_OFF);
    for (int i = tid; i < NCODES; i += 256) ees[i] = g_ee[i];

    issue_tile(g_ztb + (size_t)r0 * NC, sb + A_OFF, tid);
    issue_tile(g_cbb + (size_t)c0 * 128 * NC, sb + B_OFF + (c0 & 1) * 65536, tid);
    CP_COMMIT();

    float zzr[2][2], lb[2][2];
#pragma unroll
    for (int mt = 0; mt < 2; mt++)
#pragma unroll
        for (int h = 0; h < 2; h++) {
            int row = r0 + wm * 32 + mt * 16 + h * 8 + g4;
            zzr[mt][h] = g_zz[row];
            lb[mt][h] = __uint_as_float(g_bestu[row]);   // carry best across launches
        }

    const int lrow = ((lane >> 3) & 1) * 8 + (lane & 7);
    const int lcol = (lane >> 4) * 8;

    for (int c = c0; c < c0 + CHUNKS_PER_LAUNCH; c++) {
        CP_WAIT0();
        __syncthreads();
        if (c + 1 < c0 + CHUNKS_PER_LAUNCH)
            issue_tile(g_cbb + (size_t)(c + 1) * 128 * NC, sb + B_OFF + ((c + 1) & 1) * 65536, tid);
        CP_COMMIT();

        const uint32_t bbase = sb + B_OFF + (c & 1) * 65536;
        const uint32_t abase = sb + A_OFF;
        float acc[2][8][4];
#pragma unroll
        for (int mt = 0; mt < 2; mt++)
#pragma unroll
            for (int nt = 0; nt < 8; nt++)
#pragma unroll
                for (int e = 0; e < 4; e++) acc[mt][nt][e] = 0.f;

        // software-pipelined fragment loads (double-buffered regs)
        uint32_t a[2][2][4], b[2][4][4];
        {
            int k0 = lcol;
#pragma unroll
            for (int mt = 0; mt < 2; mt++)
                ldsm_x4(a[0][mt], tile_addr(abase, wm * 32 + mt * 16 + lrow, k0));
#pragma unroll
            for (int p = 0; p < 4; p++)
                ldsm_x4(b[0][p], tile_addr(bbase, wn * 64 + p * 16 + lrow, k0));
        }
#pragma unroll
        for (int kk = 0; kk < 16; kk++) {
            int s = kk & 1;
            if (kk < 15) {
                int k0 = (kk + 1) * 16 + lcol;
#pragma unroll
                for (int mt = 0; mt < 2; mt++)
                    ldsm_x4(a[s ^ 1][mt], tile_addr(abase, wm * 32 + mt * 16 + lrow, k0));
#pragma unroll
                for (int p = 0; p < 4; p++)
                    ldsm_x4(b[s ^ 1][p], tile_addr(bbase, wn * 64 + p * 16 + lrow, k0));
            }
#pragma unroll
            for (int mt = 0; mt < 2; mt++)
#pragma unroll
                for (int nt = 0; nt < 8; nt++) {
                    int p = nt >> 1, o = nt & 1;
                    mma16816(acc[mt][nt], a[s][mt], b[s][p][o], b[s][p][o + 2]);
                }
        }

        // epilogue: scores, per-row chunk min, candidate append
        float nb[2][2];
#pragma unroll
        for (int mt = 0; mt < 2; mt++)
#pragma unroll
            for (int h = 0; h < 2; h++) {
                float zze = zzr[mt][h];
                float m = 3.0e38f;
#pragma unroll
                for (int nt = 0; nt < 8; nt++)
#pragma unroll
                    for (int e = 0; e < 2; e++) {
                        int code = c * 128 + wn * 64 + nt * 8 + q4 * 2 + e;
                        float s = fmaf(-2.0f, acc[mt][nt][h * 2 + e], zze + ees[code]);
                        acc[mt][nt][h * 2 + e] = s;
                        m = fminf(m, s);
                    }
                m = fminf(m, __shfl_xor_sync(0xffffffffu, m, 1));
                m = fminf(m, __shfl_xor_sync(0xffffffffu, m, 2));
                nb[mt][h] = fminf(lb[mt][h], m);
            }
#pragma unroll
        for (int mt = 0; mt < 2; mt++)
#pragma unroll
            for (int h = 0; h < 2; h++) {
                float thr = nb[mt][h] + MARGIN;
                int row = r0 + wm * 32 + mt * 16 + h * 8 + g4;
#pragma unroll
                for (int nt = 0; nt < 8; nt++)
#pragma unroll
                    for (int e = 0; e < 2; e++) {
                        float s = acc[mt][nt][h * 2 + e];
                        if (s < thr) {
                            int code = c * 128 + wn * 64 + nt * 8 + q4 * 2 + e;
                            int slot = atomicAdd(&g_cnt[row], 1);
                            if (slot < CANDMAX) {
                                g_cand_s[(size_t)row * CANDMAX + slot] = s;
                                g_cand_c[(size_t)row * CANDMAX + slot] = code;
                            }
                            atomicMin(&g_bestu[row], __float_as_uint(s));
                        }
                    }
                lb[mt][h] = nb[mt][h];
            }
    }
}

// ---------------- exact fp32 rescore ----------------
__global__ void k_rescore(const float* __restrict__ cb) {
    int row = blockIdx.x * 8 + (threadIdx.x >> 5);
    int lane = threadIdx.x & 31;
    const float4* zr = reinterpret_cast<const float4*>(g_zt + (size_t)row * NC);
    float4 z0 = zr[lane * 2], z1 = zr[lane * 2 + 1];
    float zzr = g_zz[row];
    int cnt = g_cnt[row];
    float bs = __uint_as_float(g_bestu[row]);
    unsigned long long bkey = ~0ull;

    auto eval = [&](int code) {
        const float4* er = reinterpret_cast<const float4*>(cb + (size_t)code * NC);
        float4 e0 = er[lane * 2], e1 = er[lane * 2 + 1];
        float p = z0.x * e0.x + z0.y * e0.y + z0.z * e0.z + z0.w * e0.w
                + z1.x * e1.x + z1.y * e1.y + z1.z * e1.z + z1.w * e1.w;
#pragma unroll
        for (int o = 16; o > 0; o >>= 1) p += __shfl_xor_sync(0xffffffffu, p, o);
        float d = __fadd_rn(__fadd_rn(zzr, g_ee[code]), -2.0f * p);
        unsigned long long key =
            ((unsigned long long)__float_as_uint(d) << 13) | (unsigned long long)code;
        if (key < bkey) bkey = key;
    };

    if (cnt > CANDMAX) {
        for (int code = 0; code < NCODES; code++) eval(code);
    } else {
        size_t crow = (size_t)row * CANDMAX;
        for (int i = 0; i < cnt; i++) {
            float si = g_cand_s[crow + i];
            if (si > bs + MARGIN) continue;
            eval(g_cand_c[crow + i]);
        }
    }
    if (lane == 0) g_idx[row] = (int)(bkey & 8191u);
}

__global__ void k_output(const float* __restrict__ z, const float* __restrict__ cb,
                         float* __restrict__ out) {
    __shared__ float warp_s[8];
    int e = blockIdx.x * 256 + threadIdx.x;
    int t = e & 2047, bc = e >> 11, c = bc & 255, b = bc >> 8;
    int code = g_idx[b * 2048 + t];
    float v = z[e];
    float zq = cb[(size_t)code * NC + c];
    float d = zq - v;
    out[e] = v + d;
    float s = d * d;
#pragma unroll
    for (int o = 16; o > 0; o >>= 1) s += __shfl_xor_sync(0xffffffffu, s, o);
    if ((threadIdx.x & 31) == 0) warp_s[threadIdx.x >> 5] = s;
    __syncthreads();
    if (threadIdx.x == 0) {
        float acc = 0.f;
#pragma unroll
        for (int w = 0; w < 8; w++) acc += warp_s[w];
        g_losspart[blockIdx.x] = acc;
    }
}

__global__ void k_final(float* __restrict__ out) {
    if (blockIdx.x < 128) {
        int i = blockIdx.x * 256 + threadIdx.x;
        out[NQ + i] = (float)g_idx[i];
    } else {
        __shared__ double ds[256];
        double a = 0.0;
        for (int i = threadIdx.x; i < NQ / 256; i += 256) a += (double)g_losspart[i];
        ds[threadIdx.x] = a;
        __syncthreads();
        for (int o = 128; o > 0; o >>= 1) {
            if (threadIdx.x < o) ds[threadIdx.x] += ds[threadIdx.x + o];
            __syncthreads();
        }
        if (threadIdx.x == 0) out[NQ + NROWS] = (float)(ds[0] / (double)NQ);
    }
}

extern "C" void kernel_launch(void* const* d_in, const int* in_sizes, int n_in,
                              void* d_out, int out_size) {
    const float* z  = (const float*)d_in[0];
    const float* cb = (const float*)d_in[1];
    float* out = (float*)d_out;
    cudaFuncSetAttribute(k_screen, cudaFuncAttributeMaxDynamicSharedMemorySize, SMEMT);
    k_transpose<<<NROWS / 64, 256>>>(z);                       // 1
    k_prep<<<(NCODES * NC) / 256, 256>>>(cb);                  // 2
    k_norms<<<(NROWS + NCODES) / 8, 256>>>(cb);                // 3
    k_screen<<<NROWS / 128, 256, SMEMT>>>(0);                  // 4
    k_screen<<<NROWS / 128, 256, SMEMT>>>(16);                 // 5
    k_screen<<<NROWS / 128, 256, SMEMT>>>(32);                 // 6
    k_screen<<<NROWS / 128, 256, SMEMT>>>(48);                 // 7
    k_rescore<<<NROWS / 8, 256>>>(cb);                         // 8
    k_output<<<NQ / 256, 256>>>(z, cb, out);                   // 9
    k_final<<<129, 256>>>(out);                                // 10
}